// round 15
// baseline (speedup 1.0000x reference)
#include <cuda_runtime.h>
#include <cstdint>
#include <math.h>

#define Bsz 1024
#define Dm 1024
#define NH 16
#define DHd 64
#define SEQ 50
#define NOUT 1000
#define LNEPS 1e-5f
#define BT 4

// ---------------- scratch globals ------------------------------------------
__device__ float g_pe[SEQ * Dm];
__device__ float g_hh[SEQ * 16];
__device__ float g_pesum[SEQ];
__device__ float g_pesq[SEQ];
__device__ float g_G[256];
__device__ float g_cs[16];
__device__ float g_x0[Dm];
__device__ float g_tok0[Dm];
__device__ float g_vproj[NH * 16];
__device__ float g_pep[NH * SEQ];
__device__ float g_su[NH];
__device__ float g_gam[NH];
__device__ float g_sc0[NH];
__device__ float g_wvT[NH * DHd * DHd];
__device__ float g_wpT[16 * Dm];
__device__ float g_tok0p[Bsz * Dm];
// tf32 hi/lo planes
__device__ float g_aH[Bsz * Dm];
__device__ float g_aL[Bsz * Dm];
__device__ float g_fH[Bsz * Dm];
__device__ float g_fL[Bsz * Dm];
__device__ float g_WmH[Dm * Dm];
__device__ float g_WmL[Dm * Dm];
__device__ float g_WhH[NOUT * Dm];
__device__ float g_WhL[NOUT * Dm];
// split-K partials
__device__ float g_P0[Bsz * Dm];
__device__ float g_P1[Bsz * Dm];
__device__ float g_Q0[Bsz * NOUT];
__device__ float g_Q1[Bsz * NOUT];

// ---------------- helpers ----------------------------------------------------
__device__ __forceinline__ void split_tf32(float v, float& h, float& l) {
    uint32_t hu;
    asm("cvt.rna.tf32.f32 %0, %1;" : "=r"(hu) : "f"(v));
    h = __uint_as_float(hu);
    uint32_t lu;
    asm("cvt.rna.tf32.f32 %0, %1;" : "=r"(lu) : "f"(v - h));
    l = __uint_as_float(lu);
}

__device__ __forceinline__ float bred256(float v, float* red) {
    int tid = threadIdx.x, lane = tid & 31, w = tid >> 5;
    #pragma unroll
    for (int o = 16; o > 0; o >>= 1) v += __shfl_xor_sync(0xffffffffu, v, o);
    if (lane == 0) red[w] = v;
    __syncthreads();
    float r = 0.f;
    if (tid < 8) {
        r = red[tid];
        #pragma unroll
        for (int o = 4; o > 0; o >>= 1) r += __shfl_xor_sync(0xffu, r, o);
        if (tid == 0) red[0] = r;
    }
    __syncthreads();
    r = red[0];
    __syncthreads();
    return r;
}

__device__ __forceinline__ float bred_generic(float v, float* red, int nwarps) {
    int tid = threadIdx.x, lane = tid & 31, w = tid >> 5;
    #pragma unroll
    for (int o = 16; o > 0; o >>= 1) v += __shfl_xor_sync(0xffffffffu, v, o);
    if (lane == 0) red[w] = v;
    __syncthreads();
    float r = 0.f;
    if (tid < 32) {
        r = (tid < nwarps) ? red[tid] : 0.f;
        #pragma unroll
        for (int o = 16; o > 0; o >>= 1) r += __shfl_xor_sync(0xffffffffu, r, o);
        if (tid == 0) red[0] = r;
    }
    __syncthreads();
    r = red[0];
    __syncthreads();
    return r;
}

// ============================================================================
// K_PRE: batch-independent precompute, 227 independent blocks
// ============================================================================
__global__ __launch_bounds__(256) void k_pre(
    const float* __restrict__ Wp, const float* __restrict__ cls,
    const float* __restrict__ ln1w, const float* __restrict__ ln1b,
    const float* __restrict__ Wq, const float* __restrict__ bq,
    const float* __restrict__ Wk, const float* __restrict__ bk,
    const float* __restrict__ Wv, const float* __restrict__ Wm,
    const float* __restrict__ Wh)
{
    __shared__ float red[8];
    __shared__ float x0s[64], q0s[64], tvs[64], us[64], arr[64], freqs[64];
    __shared__ float hres[4];
    const int bid = blockIdx.x, tid = threadIdx.x;

    if (bid < 50) {
        int s = bid;
        float v[4];
        #pragma unroll
        for (int u = 0; u < 4; u++) {
            int d = tid + 256 * u;
            float freq = powf(10000.f, -(float)(d & ~1) / (float)Dm);
            float sa, ca;
            sincosf((float)s * freq, &sa, &ca);
            float p = (d & 1) ? ca : sa;
            g_pe[s * Dm + d] = p;
            v[u] = p;
        }
        float ps = bred256(v[0] + v[1] + v[2] + v[3], red);
        float pq = bred256(v[0]*v[0] + v[1]*v[1] + v[2]*v[2] + v[3]*v[3], red);
        if (tid == 0) { g_pesum[s] = ps; g_pesq[s] = pq; }
        for (int p = 0; p < 16; p++) {
            float a = 0.f;
            #pragma unroll
            for (int u = 0; u < 4; u++) a += Wp[(tid + 256 * u) * 16 + p] * v[u];
            float r = bred256(a, red);
            if (tid == 0) g_hh[s * 16 + p] = r;
        }
    } else if (bid < 66) {
        int p = bid - 50;
        float acc[16];
        #pragma unroll
        for (int q = 0; q < 16; q++) acc[q] = 0.f;
        float cs = 0.f;
        for (int d = tid; d < Dm; d += 256) {
            float wdp = Wp[d * 16 + p];
            cs += wdp;
            #pragma unroll
            for (int q = 0; q < 16; q++) acc[q] += wdp * Wp[d * 16 + q];
        }
        for (int q = 0; q < 16; q++) {
            float r = bred256(acc[q], red);
            if (tid == 0) g_G[p * 16 + q] = r;
        }
        float r = bred256(cs, red);
        if (tid == 0) g_cs[p] = r;
    } else if (bid == 66) {
        float v[4];
        float s1 = 0.f;
        #pragma unroll
        for (int u = 0; u < 4; u++) {
            int d = tid + 256 * u;
            float pe0 = (d & 1) ? 1.f : 0.f;
            v[u] = cls[d] + pe0;
            g_tok0[d] = v[u];
            s1 += v[u];
        }
        float mu = bred256(s1, red) * (1.0f / (float)Dm);
        float s2 = 0.f;
        #pragma unroll
        for (int u = 0; u < 4; u++) { float dv = v[u] - mu; s2 += dv * dv; }
        float var = bred256(s2, red) * (1.0f / (float)Dm);
        float rstd = rsqrtf(var + LNEPS);
        #pragma unroll
        for (int u = 0; u < 4; u++) {
            int d = tid + 256 * u;
            g_x0[d] = (v[u] - mu) * rstd * ln1w[d] + ln1b[d];
        }
    } else if (bid < 83) {
        int h = bid - 67;
        float s1 = 0.f;
        #pragma unroll
        for (int u = 0; u < 4; u++) {
            int d = tid + 256 * u;
            s1 += cls[d] + ((d & 1) ? 1.f : 0.f);
        }
        float mu = bred256(s1, red) * (1.0f / (float)Dm);
        float s2 = 0.f;
        #pragma unroll
        for (int u = 0; u < 4; u++) {
            int d = tid + 256 * u;
            float dv = cls[d] + ((d & 1) ? 1.f : 0.f) - mu;
            s2 += dv * dv;
        }
        float var = bred256(s2, red) * (1.0f / (float)Dm);
        float rstd = rsqrtf(var + LNEPS);

        if (tid < 64) {
            int gd = h * DHd + tid;
            float val = cls[gd] + ((gd & 1) ? 1.f : 0.f);
            x0s[tid] = (val - mu) * rstd * ln1w[gd] + ln1b[gd];
            freqs[tid] = powf(10000.f, -(float)(gd & ~1) / (float)Dm);
        }
        __syncthreads();

        if (tid < 64) {
            float a = bq[h * DHd + tid];
            const float* wr = &Wq[(h * DHd + tid) * DHd];
            #pragma unroll 16
            for (int d = 0; d < DHd; d++) a += wr[d] * x0s[d];
            q0s[tid] = a;
        }
        __syncthreads();

        if (tid < 64) arr[tid] = q0s[tid] * bk[h * DHd + tid];
        __syncthreads();
        if (tid < 32) {
            float a = arr[tid] + arr[tid + 32];
            #pragma unroll
            for (int o = 16; o > 0; o >>= 1) a += __shfl_down_sync(0xffffffffu, a, o);
            if (tid == 0) hres[0] = a;
        }
        __syncthreads();

        if (tid < 64) {
            float a = 0.f;
            #pragma unroll 16
            for (int d = 0; d < DHd; d++) a += q0s[d] * Wk[(h * DHd + d) * DHd + tid];
            tvs[tid] = a;
            us[tid] = a * ln1w[h * DHd + tid];
        }
        __syncthreads();

        if (tid < 64) arr[tid] = us[tid];
        __syncthreads();
        if (tid < 32) {
            float a = arr[tid] + arr[tid + 32];
            #pragma unroll
            for (int o = 16; o > 0; o >>= 1) a += __shfl_down_sync(0xffffffffu, a, o);
            if (tid == 0) hres[1] = a;
        }
        __syncthreads();
        if (tid < 64) arr[tid] = tvs[tid] * ln1b[h * DHd + tid];
        __syncthreads();
        if (tid < 32) {
            float a = arr[tid] + arr[tid + 32];
            #pragma unroll
            for (int o = 16; o > 0; o >>= 1) a += __shfl_down_sync(0xffffffffu, a, o);
            if (tid == 0) hres[2] = a;
        }
        __syncthreads();
        if (tid < 64) arr[tid] = tvs[tid] * x0s[tid];
        __syncthreads();
        if (tid < 32) {
            float a = arr[tid] + arr[tid + 32];
            #pragma unroll
            for (int o = 16; o > 0; o >>= 1) a += __shfl_down_sync(0xffffffffu, a, o);
            if (tid == 0) hres[3] = a;
        }
        __syncthreads();

        if (tid == 0) {
            g_su[h]  = hres[1];
            g_gam[h] = hres[2] + hres[0];
            g_sc0[h] = 32.0f * (hres[3] + hres[0]);
        }
        if (tid < 16) {
            float a = 0.f;
            #pragma unroll 16
            for (int d = 0; d < DHd; d++) a += us[d] * Wp[(h * DHd + d) * 16 + tid];
            g_vproj[h * 16 + tid] = a;
        }
        if (tid < SEQ) {
            int s = tid;
            float a = 0.f;
            for (int d = 0; d < DHd; d++) {
                int gd = h * DHd + d;
                float sa, ca;
                sincosf((float)s * freqs[d], &sa, &ca);
                a += us[d] * ((gd & 1) ? ca : sa);
            }
            g_pep[h * SEQ + s] = a;
        }
    } else if (bid < 99) {
        int h = bid - 83;
        for (int idx = tid; idx < DHd * DHd; idx += 256) {
            int e = idx >> 6, d = idx & 63;
            g_wvT[h * DHd * DHd + d * DHd + e] = Wv[(h * DHd + e) * DHd + d];
        }
    } else if (bid == 99) {
        for (int idx = tid; idx < 16 * Dm; idx += 256) {
            int gd = idx >> 4, p = idx & 15;
            g_wpT[p * Dm + gd] = Wp[gd * 16 + p];
        }
    } else if (bid < 164) {
        int base4 = (bid - 100) * 4096;
        for (int i4 = tid; i4 < 4096; i4 += 256) {
            float4 v = ((const float4*)Wm)[base4 + i4];
            float4 h4, l4;
            split_tf32(v.x, h4.x, l4.x);
            split_tf32(v.y, h4.y, l4.y);
            split_tf32(v.z, h4.z, l4.z);
            split_tf32(v.w, h4.w, l4.w);
            ((float4*)g_WmH)[base4 + i4] = h4;
            ((float4*)g_WmL)[base4 + i4] = l4;
        }
    } else {
        int base4 = (bid - 164) * 4096;
        const int tot4 = NOUT * Dm / 4;
        for (int i4 = tid; i4 < 4096; i4 += 256) {
            int idx4 = base4 + i4;
            if (idx4 < tot4) {
                float4 v = ((const float4*)Wh)[idx4];
                float4 h4, l4;
                split_tf32(v.x, h4.x, l4.x);
                split_tf32(v.y, h4.y, l4.y);
                split_tf32(v.z, h4.z, l4.z);
                split_tf32(v.w, h4.w, l4.w);
                ((float4*)g_WhH)[idx4] = h4;
                ((float4*)g_WhL)[idx4] = l4;
            }
        }
    }
}

// ============================================================================
// K_MAIN: per-batch kernel, BT=4 per block; phase 8 emits tf32 hi/lo planes.
// ============================================================================
#define OFF_PA   0
#define OFF_SCR  (OFF_PA + BT*784)
#define OFF_MU   (OFF_SCR + BT*832)
#define OFF_RSD  (OFF_MU + BT*50)
#define OFF_QT   (OFF_RSD + BT*50)
#define OFF_CC   (OFF_QT + BT*256)
#define OFF_T0P  (OFF_CC + BT*1024)
#define OFF_P0   (OFF_T0P + BT*1024)
#define OFF_MB   (OFF_P0 + BT*16)
#define OFF_RED2 (OFF_MB + BT*16)
#define KMAIN_FLOATS (OFF_RED2 + 16)
#define KMAIN_SMEM (KMAIN_FLOATS * 4)

__global__ __launch_bounds__(512) void k_main(
    const float* __restrict__ x,
    const float* __restrict__ ln1w, const float* __restrict__ ln1b,
    const float* __restrict__ bv,
    const float* __restrict__ ln2w, const float* __restrict__ ln2b)
{
    extern __shared__ float sm[];
    float* pa    = sm + OFF_PA;
    float* scr   = sm + OFF_SCR;
    float* mu    = sm + OFF_MU;
    float* rsd   = sm + OFF_RSD;
    float* qt    = sm + OFF_QT;
    float* cc    = sm + OFF_CC;
    float* t0p   = sm + OFF_T0P;
    float* p0s   = sm + OFF_P0;
    float* mbars = sm + OFF_MB;
    float* red   = sm + OFF_RED2;

    const int b0  = blockIdx.x * BT;
    const int tid = threadIdx.x;
    const int w = tid >> 5, lane = tid & 31;

    if (tid < BT) { mu[tid * 50] = 0.f; rsd[tid * 50] = 0.f; }
    for (int idx = tid; idx < BT * 784; idx += 512) {
        int bt = idx / 784, r = idx % 784;
        int row = r / 28, col = r % 28;
        int pi = (row >> 2) * 7 + (col >> 2);
        int pp = (row & 3) * 4 + (col & 3);
        pa[bt * 784 + pi * 16 + pp] = x[(size_t)(b0 + bt) * 784 + r];
    }
    __syncthreads();

    for (int t = w * 2 + (lane >> 4); t < BT * 49; t += 32) {
        int bt = t / 49, sidx = t % 49, s = sidx + 1;
        int p = lane & 15;
        const float* pr = &pa[bt * 784 + sidx * 16];
        float pap = pr[p];
        float y = 0.f;
        #pragma unroll
        for (int q = 0; q < 16; q++) y += g_G[p * 16 + q] * pr[q];
        float e2p = pap * (y + 2.0f * g_hh[s * 16 + p]);
        float mup = pap * g_cs[p];
        #pragma unroll
        for (int o = 8; o > 0; o >>= 1) {
            e2p += __shfl_down_sync(0xffffffffu, e2p, o, 16);
            mup += __shfl_down_sync(0xffffffffu, mup, o, 16);
        }
        if (p == 0) {
            float m = (mup + g_pesum[s]) * (1.0f / (float)Dm);
            float var = (e2p + g_pesq[s]) * (1.0f / (float)Dm) - m * m;
            mu[bt * 50 + s] = m;
            rsd[bt * 50 + s] = rsqrtf(var + LNEPS);
        }
    }
    __syncthreads();

    for (int t = tid; t < BT * NH * SEQ; t += 512) {
        int bt = t / (NH * SEQ), rem = t % (NH * SEQ);
        int h = rem / SEQ, s = rem % SEQ;
        float v;
        if (s == 0) {
            v = g_sc0[h];
        } else {
            float g = g_pep[h * SEQ + s];
            const float* pr = &pa[bt * 784 + (s - 1) * 16];
            const float* vp = &g_vproj[h * 16];
            #pragma unroll
            for (int p = 0; p < 16; p++) g += pr[p] * vp[p];
            v = 32.0f * (rsd[bt * 50 + s] * (g - mu[bt * 50 + s] * g_su[h]) + g_gam[h]);
        }
        scr[bt * 832 + h * 52 + s] = v;
    }
    __syncthreads();

    for (int task = w; task < BT * NH; task += 16) {
        int bt = task >> 4, h = task & 15;
        float* row = &scr[bt * 832 + h * 52];
        float v1 = row[lane];
        float v2 = (lane + 32 < SEQ) ? row[lane + 32] : -INFINITY;
        float m = fmaxf(v1, v2);
        #pragma unroll
        for (int o = 16; o > 0; o >>= 1) m = fmaxf(m, __shfl_xor_sync(0xffffffffu, m, o));
        float e1 = expf(v1 - m);
        float e2 = (lane + 32 < SEQ) ? expf(v2 - m) : 0.f;
        float ss = e1 + e2;
        #pragma unroll
        for (int o = 16; o > 0; o >>= 1) ss += __shfl_xor_sync(0xffffffffu, ss, o);
        float inv = 1.0f / ss;
        float p1 = e1 * inv, p2 = e2 * inv;
        float r1 = (lane == 0) ? 0.f : p1 * rsd[bt * 50 + lane];
        float r2 = (lane + 32 < SEQ) ? p2 * rsd[bt * 50 + lane + 32] : 0.f;
        row[lane] = r1;
        if (lane + 32 < SEQ) row[lane + 32] = r2;
        float mb = r1 * mu[bt * 50 + lane]
                 + ((lane + 32 < SEQ) ? r2 * mu[bt * 50 + lane + 32] : 0.f);
        #pragma unroll
        for (int o = 16; o > 0; o >>= 1) mb += __shfl_xor_sync(0xffffffffu, mb, o);
        if (lane == 0) { mbars[bt * 16 + h] = mb; p0s[bt * 16 + h] = p1; }
    }
    __syncthreads();

    for (int task = w; task < BT * NH; task += 16) {
        int bt = task >> 4, h = task & 15;
        if (lane < 16) {
            int p = lane;
            const float* rr = &scr[bt * 832 + h * 52];
            const float* pb = &pa[bt * 784];
            float a = 0.f;
            #pragma unroll 7
            for (int sidx = 0; sidx < 49; sidx++)
                a += rr[sidx + 1] * pb[sidx * 16 + p];
            qt[bt * 256 + h * 16 + p] = a;
        }
    }
    __syncthreads();

    for (int gd = tid; gd < Dm; gd += 512) {
        int h = gd >> 6;
        float t1[BT], t2[BT];
        #pragma unroll
        for (int bt = 0; bt < BT; bt++) { t1[bt] = 0.f; t2[bt] = 0.f; }
        #pragma unroll
        for (int p = 0; p < 16; p++) {
            float wv = g_wpT[p * Dm + gd];
            #pragma unroll
            for (int bt = 0; bt < BT; bt++)
                t1[bt] += qt[bt * 256 + h * 16 + p] * wv;
        }
        #pragma unroll 7
        for (int s = 1; s < SEQ; s++) {
            float pev = g_pe[s * Dm + gd];
            #pragma unroll
            for (int bt = 0; bt < BT; bt++)
                t2[bt] += scr[bt * 832 + h * 52 + s] * pev;
        }
        float w1 = ln1w[gd], bb = ln1b[gd], xx0 = g_x0[gd];
        #pragma unroll
        for (int bt = 0; bt < BT; bt++) {
            float p0 = p0s[bt * 16 + h];
            cc[bt * 1024 + gd] = w1 * (t1[bt] + t2[bt] - mbars[bt * 16 + h])
                               + (1.0f - p0) * bb + p0 * xx0;
        }
    }
    __syncthreads();

    for (int ge = tid; ge < Dm; ge += 512) {
        int h = ge >> 6, e = ge & 63;
        float a[BT];
        float bve = bv[ge];
        #pragma unroll
        for (int bt = 0; bt < BT; bt++) a[bt] = bve;
        const float* wvt = &g_wvT[h * DHd * DHd + e];
        #pragma unroll 8
        for (int d = 0; d < DHd; d++) {
            float wvd = wvt[d * DHd];
            #pragma unroll
            for (int bt = 0; bt < BT; bt++)
                a[bt] += wvd * cc[bt * 1024 + h * DHd + d];
        }
        float tk0 = g_tok0[ge];
        #pragma unroll
        for (int bt = 0; bt < BT; bt++)
            t0p[bt * 1024 + ge] = tk0 + a[bt];
    }
    __syncthreads();

    for (int bt = 0; bt < BT; bt++) {
        float v0 = t0p[bt * 1024 + tid], v1 = t0p[bt * 1024 + tid + 512];
        float s = bred_generic(v0 + v1, red, 16);
        float m = s * (1.0f / (float)Dm);
        float d0 = v0 - m, d1 = v1 - m;
        float q = bred_generic(d0 * d0 + d1 * d1, red, 16);
        float rstd = rsqrtf(q * (1.0f / (float)Dm) + LNEPS);
        size_t base = (size_t)(b0 + bt) * Dm;
        g_tok0p[base + tid]       = v0;
        g_tok0p[base + tid + 512] = v1;
        float n0a = d0 * rstd * ln2w[tid] + ln2b[tid];
        float n0b = d1 * rstd * ln2w[tid + 512] + ln2b[tid + 512];
        float ha, la, hb, lb;
        split_tf32(n0a, ha, la);
        split_tf32(n0b, hb, lb);
        g_aH[base + tid]       = ha;
        g_aL[base + tid]       = la;
        g_aH[base + tid + 512] = hb;
        g_aL[base + tid + 512] = lb;
    }
}

// ============================================================================
// GEMM (3xTF32, pre-split planes, cp.async, SPLIT-K=2).
// 64x64 CTA tile, 4 warps (32x32), BK=16. Grid (nx, ny, 2): z = K-half.
// Writes fp32 partials (no bias/res) to P0 or P1 by z.
// ============================================================================
__device__ __forceinline__ void mma_tf32(float c[4], const uint32_t a[4],
                                         const uint32_t b[2]) {
    asm volatile(
        "mma.sync.aligned.m16n8k8.row.col.f32.tf32.tf32.f32 "
        "{%0,%1,%2,%3}, {%4,%5,%6,%7}, {%8,%9}, {%0,%1,%2,%3};\n"
        : "+f"(c[0]), "+f"(c[1]), "+f"(c[2]), "+f"(c[3])
        : "r"(a[0]), "r"(a[1]), "r"(a[2]), "r"(a[3]), "r"(b[0]), "r"(b[1]));
}

__device__ __forceinline__ uint32_t smem_u32g(const void* p) {
    uint32_t a;
    asm("{ .reg .u64 t; cvta.to.shared.u64 t, %1; cvt.u32.u64 %0, t; }"
        : "=r"(a) : "l"(p));
    return a;
}

__device__ __forceinline__ void cpa16(uint32_t dst, const float* src, int ssz) {
    asm volatile("cp.async.cg.shared.global [%0], [%1], 16, %2;"
                 :: "r"(dst), "l"(src), "r"(ssz) : "memory");
}

__device__ __forceinline__ void tc_comp_rm(
    const float* Ahp, const float* Alp, const float* Bhp, const float* Blp,
    float (&c)[2][4][4], int wm, int wn, int gid, int tg)
{
    #pragma unroll
    for (int ks = 0; ks < 16; ks += 8) {
        uint32_t ah[2][4], al[2][4], bh[4][2], bl[4][2];
        #pragma unroll
        for (int i = 0; i < 2; i++) {
            int m = wm + i * 16 + gid;
            ah[i][0] = __float_as_uint(Ahp[m * 20 + ks + tg]);
            ah[i][1] = __float_as_uint(Ahp[(m + 8) * 20 + ks + tg]);
            ah[i][2] = __float_as_uint(Ahp[m * 20 + ks + tg + 4]);
            ah[i][3] = __float_as_uint(Ahp[(m + 8) * 20 + ks + tg + 4]);
            al[i][0] = __float_as_uint(Alp[m * 20 + ks + tg]);
            al[i][1] = __float_as_uint(Alp[(m + 8) * 20 + ks + tg]);
            al[i][2] = __float_as_uint(Alp[m * 20 + ks + tg + 4]);
            al[i][3] = __float_as_uint(Alp[(m + 8) * 20 + ks + tg + 4]);
        }
        #pragma unroll
        for (int j = 0; j < 4; j++) {
            int n = wn + j * 8 + gid;
            bh[j][0] = __float_as_uint(Bhp[n * 20 + ks + tg]);
            bh[j][1] = __float_as_uint(Bhp[n * 20 + ks + tg + 4]);
            bl[j][0] = __float_as_uint(Blp[n * 20 + ks + tg]);
            bl[j][1] = __float_as_uint(Blp[n * 20 + ks + tg + 4]);
        }
        #pragma unroll
        for (int i = 0; i < 2; i++)
            #pragma unroll
            for (int j = 0; j < 4; j++) {
                mma_tf32(c[i][j], ah[i], bh[j]);
                mma_tf32(c[i][j], ah[i], bl[j]);
                mma_tf32(c[i][j], al[i], bh[j]);
            }
    }
}

__global__ __launch_bounds__(128) void gemm_sk(
    const float* __restrict__ AH, const float* __restrict__ AL,
    const float* __restrict__ BH, const float* __restrict__ BL,
    float* __restrict__ P0, float* __restrict__ P1,
    int M, int N, int K)
{
    __shared__ float smbuf[2 * 4 * 1280];   // 40960 B
    const int tid = threadIdx.x;
    const int warp = tid >> 5, lane = tid & 31;
    const int wm = (warp & 1) * 32, wn = (warp >> 1) * 32;
    const int m0 = blockIdx.y * 64, n0 = blockIdx.x * 64;
    const int kbase = blockIdx.z * (K >> 1);
    float* Pout = blockIdx.z ? P1 : P0;
    const int gid = lane >> 2, tg = lane & 3;

    float c[2][4][4];
    #pragma unroll
    for (int i = 0; i < 2; i++)
        #pragma unroll
        for (int j = 0; j < 4; j++)
            #pragma unroll
            for (int q = 0; q < 4; q++) c[i][j][q] = 0.f;

    const int r0 = tid >> 1;
    const int q0 = (tid & 1) * 2;
    const float* gAH = AH + (size_t)(m0 + r0) * K + kbase + q0 * 4;
    const float* gAL = AL + (size_t)(m0 + r0) * K + kbase + q0 * 4;
    const int nr = n0 + r0;
    const int nok = (nr < N) ? 16 : 0;
    const float* gBH = BH + (size_t)(nr < N ? nr : 0) * K + kbase + q0 * 4;
    const float* gBL = BL + (size_t)(nr < N ? nr : 0) * K + kbase + q0 * 4;

    const uint32_t dst0 = smem_u32g(smbuf) + (uint32_t)(r0 * 20 + q0 * 4) * 4u;

    {
        cpa16(dst0,             gAH, 16);
        cpa16(dst0 + 16,        gAH + 4, 16);
        cpa16(dst0 + 5120,      gAL, 16);
        cpa16(dst0 + 5136,      gAL + 4, 16);
        cpa16(dst0 + 10240,     gBH, nok);
        cpa16(dst0 + 10256,     gBH + 4, nok);
        cpa16(dst0 + 15360,     gBL, nok);
        cpa16(dst0 + 15376,     gBL + 4, nok);
        asm volatile("cp.async.commit_group;" ::: "memory");
    }

    const int NSLAB = (K >> 1) / 16;   // 32
    for (int s = 0; s < NSLAB; s++) {
        asm volatile("cp.async.wait_group 0;" ::: "memory");
        __syncthreads();
        if (s + 1 < NSLAB) {
            int koff = (s + 1) * 16;
            uint32_t d = dst0 + (uint32_t)((s + 1) & 1) * 20480u;
            cpa16(d,             gAH + koff, 16);
            cpa16(d + 16,        gAH + koff + 4, 16);
            cpa16(d + 5120,      gAL + koff, 16);
            cpa16(d + 5136,      gAL + koff + 4, 16);
            cpa16(d + 10240,     gBH + koff, nok);
            cpa16(d + 10256,     gBH + koff + 4, nok);
            cpa16(d + 15360,     gBL + koff, nok);
            cpa16(d + 15376,     gBL + koff + 4, nok);
            asm volatile("cp.async.commit_group;" ::: "memory");
        }
        const float* base = smbuf + (s & 1) * 5120;
        tc_comp_rm(base, base + 1280, base + 2560, base + 3840,
                   c, wm, wn, gid, tg);
    }

    // epilogue: raw partial store
    #pragma unroll
    for (int i = 0; i < 2; i++) {
        #pragma unroll
        for (int j = 0; j < 4; j++) {
            int row0 = m0 + wm + i * 16 + gid;
            int col0 = n0 + wn + j * 8 + 2 * tg;
            #pragma unroll
            for (int q = 0; q < 4; q++) {
                int row = row0 + (q >> 1) * 8;
                int col = col0 + (q & 1);
                if (col < N)
                    Pout[(size_t)row * N + col] = c[i][j][q];
            }
        }
    }
}

// ============================================================================
// K_FIX1: C = P0+P1+bm+Res -> split to tf32 planes (feeds gemm2)
// ============================================================================
__global__ __launch_bounds__(256) void k_fix1(
    const float* __restrict__ bm)
{
    int b = blockIdx.x, tid = threadIdx.x;
    size_t base = (size_t)b * Dm;
    #pragma unroll
    for (int u = 0; u < 4; u++) {
        int j = tid + 256 * u;
        float v = g_P0[base + j] + g_P1[base + j] + bm[j] + g_tok0p[base + j];
        float h, l;
        split_tf32(v, h, l);
        g_fH[base + j] = h;
        g_fL[base + j] = l;
    }
}

// ---------------- softmax over 1000 logits (reads Q0+Q1+bias) ---------------
__global__ __launch_bounds__(256) void softmax_kernel(
    const float* __restrict__ bh, float* __restrict__ out)
{
    int b = blockIdx.x, tid = threadIdx.x;
    __shared__ float red[32];
    int lane = tid & 31, w = tid >> 5;
    size_t base = (size_t)b * NOUT;
    float v[4];
    float m = -INFINITY;
    #pragma unroll
    for (int u = 0; u < 4; u++) {
        int j = tid + 256 * u;
        v[u] = (j < NOUT) ? (g_Q0[base + j] + g_Q1[base + j] + bh[j]) : -INFINITY;
        m = fmaxf(m, v[u]);
    }
    #pragma unroll
    for (int o = 16; o > 0; o >>= 1) m = fmaxf(m, __shfl_xor_sync(0xffffffffu, m, o));
    if (lane == 0) red[w] = m;
    __syncthreads();
    if (tid < 8) {
        float x2 = red[tid];
        #pragma unroll
        for (int o = 4; o > 0; o >>= 1) x2 = fmaxf(x2, __shfl_xor_sync(0xffu, x2, o));
        if (tid == 0) red[0] = x2;
    }
    __syncthreads();
    m = red[0];
    __syncthreads();
    float s = 0.f;
    #pragma unroll
    for (int u = 0; u < 4; u++) {
        int j = tid + 256 * u;
        if (j < NOUT) { v[u] = expf(v[u] - m); s += v[u]; }
    }
    #pragma unroll
    for (int o = 16; o > 0; o >>= 1) s += __shfl_xor_sync(0xffffffffu, s, o);
    if (lane == 0) red[w] = s;
    __syncthreads();
    if (tid < 8) {
        float x2 = red[tid];
        #pragma unroll
        for (int o = 4; o > 0; o >>= 1) x2 += __shfl_xor_sync(0xffu, x2, o);
        if (tid == 0) red[0] = x2;
    }
    __syncthreads();
    float inv = 1.0f / red[0];
    #pragma unroll
    for (int u = 0; u < 4; u++) {
        int j = tid + 256 * u;
        if (j < NOUT) out[base + j] = v[u] * inv;
    }
}

// ---------------- launch ------------------------------------------------------
extern "C" void kernel_launch(void* const* d_in, const int* in_sizes, int n_in,
                              void* d_out, int out_size) {
    const float* x    = (const float*)d_in[0];
    const float* cls  = (const float*)d_in[1];
    const float* Wp   = (const float*)d_in[2];
    const float* ln1w = (const float*)d_in[3];
    const float* ln1b = (const float*)d_in[4];
    const float* Wq   = (const float*)d_in[5];
    const float* bq   = (const float*)d_in[6];
    const float* Wk   = (const float*)d_in[7];
    const float* bk   = (const float*)d_in[8];
    const float* Wv   = (const float*)d_in[9];
    const float* bv   = (const float*)d_in[10];
    const float* ln2w = (const float*)d_in[11];
    const float* ln2b = (const float*)d_in[12];
    const float* Wm   = (const float*)d_in[13];
    const float* bm   = (const float*)d_in[14];
    const float* Wh   = (const float*)d_in[15];
    const float* bh   = (const float*)d_in[16];
    float* out = (float*)d_out;

    float *p_aH, *p_aL, *p_fH, *p_fL, *p_WmH, *p_WmL, *p_WhH, *p_WhL;
    float *p_P0, *p_P1, *p_Q0, *p_Q1;
    cudaGetSymbolAddress((void**)&p_aH, g_aH);
    cudaGetSymbolAddress((void**)&p_aL, g_aL);
    cudaGetSymbolAddress((void**)&p_fH, g_fH);
    cudaGetSymbolAddress((void**)&p_fL, g_fL);
    cudaGetSymbolAddress((void**)&p_WmH, g_WmH);
    cudaGetSymbolAddress((void**)&p_WmL, g_WmL);
    cudaGetSymbolAddress((void**)&p_WhH, g_WhH);
    cudaGetSymbolAddress((void**)&p_WhL, g_WhL);
    cudaGetSymbolAddress((void**)&p_P0, g_P0);
    cudaGetSymbolAddress((void**)&p_P1, g_P1);
    cudaGetSymbolAddress((void**)&p_Q0, g_Q0);
    cudaGetSymbolAddress((void**)&p_Q1, g_Q1);

    cudaFuncSetAttribute(k_main, cudaFuncAttributeMaxDynamicSharedMemorySize,
                         KMAIN_SMEM);

    k_pre<<<227, 256>>>(Wp, cls, ln1w, ln1b, Wq, bq, Wk, bk, Wv, Wm, Wh);
    k_main<<<Bsz / BT, 512, KMAIN_SMEM>>>(x, ln1w, ln1b, bv, ln2w, ln2b);
    gemm_sk<<<dim3(16, 16, 2), 128>>>(
        p_aH, p_aL, p_WmH, p_WmL, p_P0, p_P1, Bsz, Dm, Dm);
    k_fix1<<<Bsz, 256>>>(bm);
    gemm_sk<<<dim3(16, 16, 2), 128>>>(
        p_fH, p_fL, p_WhH, p_WhL, p_Q0, p_Q1, Bsz, NOUT, Dm);
    softmax_kernel<<<Bsz, 256>>>(bh, out);
}

// round 16
// speedup vs baseline: 1.5294x; 1.5294x over previous
#include <cuda_runtime.h>
#include <cuda_fp16.h>
#include <cstdint>
#include <math.h>

#define Bsz 1024
#define Dm 1024
#define NH 16
#define DHd 64
#define SEQ 50
#define NOUT 1000
#define LNEPS 1e-5f
#define BT 4

// ---------------- scratch globals ------------------------------------------
__device__ float g_pe[SEQ * Dm];
__device__ float g_hh[SEQ * 16];
__device__ float g_pesum[SEQ];
__device__ float g_pesq[SEQ];
__device__ float g_G[256];
__device__ float g_cs[16];
__device__ float g_x0[Dm];
__device__ float g_tok0[Dm];
__device__ float g_vproj[NH * 16];
__device__ float g_pep[NH * SEQ];
__device__ float g_su[NH];
__device__ float g_gam[NH];
__device__ float g_sc0[NH];
__device__ float g_wvT[NH * DHd * DHd];
__device__ float g_wpT[16 * Dm];
__device__ float g_tok0p[Bsz * Dm];
// fp16 hi/lo packed planes (half2 per uint32, pairs along K)
__device__ uint32_t g_aHp[Bsz * Dm / 2];
__device__ uint32_t g_aLp[Bsz * Dm / 2];
__device__ uint32_t g_fHp[Bsz * Dm / 2];
__device__ uint32_t g_fLp[Bsz * Dm / 2];
__device__ uint32_t g_WmHp[Dm * Dm / 2];
__device__ uint32_t g_WmLp[Dm * Dm / 2];
__device__ uint32_t g_WhHp[NOUT * Dm / 2];
__device__ uint32_t g_WhLp[NOUT * Dm / 2];

// ---------------- helpers ----------------------------------------------------
__device__ __forceinline__ uint32_t pack2h(float a, float b) {
    __half ha = __float2half_rn(a), hb = __float2half_rn(b);
    return (uint32_t)__half_as_ushort(ha) | ((uint32_t)__half_as_ushort(hb) << 16);
}

__device__ __forceinline__ void split_h2(float a, float b,
                                         uint32_t& hi, uint32_t& lo) {
    __half ha = __float2half_rn(a), hb = __float2half_rn(b);
    float ra = a - __half2float(ha), rb = b - __half2float(hb);
    hi = (uint32_t)__half_as_ushort(ha) | ((uint32_t)__half_as_ushort(hb) << 16);
    lo = pack2h(ra, rb);
}

__device__ __forceinline__ float bred256(float v, float* red) {
    int tid = threadIdx.x, lane = tid & 31, w = tid >> 5;
    #pragma unroll
    for (int o = 16; o > 0; o >>= 1) v += __shfl_xor_sync(0xffffffffu, v, o);
    if (lane == 0) red[w] = v;
    __syncthreads();
    float r = 0.f;
    if (tid < 8) {
        r = red[tid];
        #pragma unroll
        for (int o = 4; o > 0; o >>= 1) r += __shfl_xor_sync(0xffu, r, o);
        if (tid == 0) red[0] = r;
    }
    __syncthreads();
    r = red[0];
    __syncthreads();
    return r;
}

__device__ __forceinline__ float bred_generic(float v, float* red, int nwarps) {
    int tid = threadIdx.x, lane = tid & 31, w = tid >> 5;
    #pragma unroll
    for (int o = 16; o > 0; o >>= 1) v += __shfl_xor_sync(0xffffffffu, v, o);
    if (lane == 0) red[w] = v;
    __syncthreads();
    float r = 0.f;
    if (tid < 32) {
        r = (tid < nwarps) ? red[tid] : 0.f;
        #pragma unroll
        for (int o = 16; o > 0; o >>= 1) r += __shfl_xor_sync(0xffffffffu, r, o);
        if (tid == 0) red[0] = r;
    }
    __syncthreads();
    r = red[0];
    __syncthreads();
    return r;
}

// ============================================================================
// K_PRE: batch-independent precompute, 227 independent blocks
//   0..49 pe | 50..65 Gram | 66 tok0 | 67..82 heads | 83..98 WvT | 99 WpT
//   100..163 Wm fp16 split | 164..226 Wh fp16 split
// ============================================================================
__global__ __launch_bounds__(256) void k_pre(
    const float* __restrict__ Wp, const float* __restrict__ cls,
    const float* __restrict__ ln1w, const float* __restrict__ ln1b,
    const float* __restrict__ Wq, const float* __restrict__ bq,
    const float* __restrict__ Wk, const float* __restrict__ bk,
    const float* __restrict__ Wv, const float* __restrict__ Wm,
    const float* __restrict__ Wh)
{
    __shared__ float red[8];
    __shared__ float x0s[64], q0s[64], tvs[64], us[64], arr[64], freqs[64];
    __shared__ float hres[4];
    const int bid = blockIdx.x, tid = threadIdx.x;

    if (bid < 50) {
        int s = bid;
        float v[4];
        #pragma unroll
        for (int u = 0; u < 4; u++) {
            int d = tid + 256 * u;
            float freq = powf(10000.f, -(float)(d & ~1) / (float)Dm);
            float sa, ca;
            sincosf((float)s * freq, &sa, &ca);
            float p = (d & 1) ? ca : sa;
            g_pe[s * Dm + d] = p;
            v[u] = p;
        }
        float ps = bred256(v[0] + v[1] + v[2] + v[3], red);
        float pq = bred256(v[0]*v[0] + v[1]*v[1] + v[2]*v[2] + v[3]*v[3], red);
        if (tid == 0) { g_pesum[s] = ps; g_pesq[s] = pq; }
        for (int p = 0; p < 16; p++) {
            float a = 0.f;
            #pragma unroll
            for (int u = 0; u < 4; u++) a += Wp[(tid + 256 * u) * 16 + p] * v[u];
            float r = bred256(a, red);
            if (tid == 0) g_hh[s * 16 + p] = r;
        }
    } else if (bid < 66) {
        int p = bid - 50;
        float acc[16];
        #pragma unroll
        for (int q = 0; q < 16; q++) acc[q] = 0.f;
        float cs = 0.f;
        for (int d = tid; d < Dm; d += 256) {
            float wdp = Wp[d * 16 + p];
            cs += wdp;
            #pragma unroll
            for (int q = 0; q < 16; q++) acc[q] += wdp * Wp[d * 16 + q];
        }
        for (int q = 0; q < 16; q++) {
            float r = bred256(acc[q], red);
            if (tid == 0) g_G[p * 16 + q] = r;
        }
        float r = bred256(cs, red);
        if (tid == 0) g_cs[p] = r;
    } else if (bid == 66) {
        float v[4];
        float s1 = 0.f;
        #pragma unroll
        for (int u = 0; u < 4; u++) {
            int d = tid + 256 * u;
            float pe0 = (d & 1) ? 1.f : 0.f;
            v[u] = cls[d] + pe0;
            g_tok0[d] = v[u];
            s1 += v[u];
        }
        float mu = bred256(s1, red) * (1.0f / (float)Dm);
        float s2 = 0.f;
        #pragma unroll
        for (int u = 0; u < 4; u++) { float dv = v[u] - mu; s2 += dv * dv; }
        float var = bred256(s2, red) * (1.0f / (float)Dm);
        float rstd = rsqrtf(var + LNEPS);
        #pragma unroll
        for (int u = 0; u < 4; u++) {
            int d = tid + 256 * u;
            g_x0[d] = (v[u] - mu) * rstd * ln1w[d] + ln1b[d];
        }
    } else if (bid < 83) {
        int h = bid - 67;
        float s1 = 0.f;
        #pragma unroll
        for (int u = 0; u < 4; u++) {
            int d = tid + 256 * u;
            s1 += cls[d] + ((d & 1) ? 1.f : 0.f);
        }
        float mu = bred256(s1, red) * (1.0f / (float)Dm);
        float s2 = 0.f;
        #pragma unroll
        for (int u = 0; u < 4; u++) {
            int d = tid + 256 * u;
            float dv = cls[d] + ((d & 1) ? 1.f : 0.f) - mu;
            s2 += dv * dv;
        }
        float var = bred256(s2, red) * (1.0f / (float)Dm);
        float rstd = rsqrtf(var + LNEPS);

        if (tid < 64) {
            int gd = h * DHd + tid;
            float val = cls[gd] + ((gd & 1) ? 1.f : 0.f);
            x0s[tid] = (val - mu) * rstd * ln1w[gd] + ln1b[gd];
            freqs[tid] = powf(10000.f, -(float)(gd & ~1) / (float)Dm);
        }
        __syncthreads();

        if (tid < 64) {
            float a = bq[h * DHd + tid];
            const float* wr = &Wq[(h * DHd + tid) * DHd];
            #pragma unroll 16
            for (int d = 0; d < DHd; d++) a += wr[d] * x0s[d];
            q0s[tid] = a;
        }
        __syncthreads();

        if (tid < 64) arr[tid] = q0s[tid] * bk[h * DHd + tid];
        __syncthreads();
        if (tid < 32) {
            float a = arr[tid] + arr[tid + 32];
            #pragma unroll
            for (int o = 16; o > 0; o >>= 1) a += __shfl_down_sync(0xffffffffu, a, o);
            if (tid == 0) hres[0] = a;
        }
        __syncthreads();

        if (tid < 64) {
            float a = 0.f;
            #pragma unroll 16
            for (int d = 0; d < DHd; d++) a += q0s[d] * Wk[(h * DHd + d) * DHd + tid];
            tvs[tid] = a;
            us[tid] = a * ln1w[h * DHd + tid];
        }
        __syncthreads();

        if (tid < 64) arr[tid] = us[tid];
        __syncthreads();
        if (tid < 32) {
            float a = arr[tid] + arr[tid + 32];
            #pragma unroll
            for (int o = 16; o > 0; o >>= 1) a += __shfl_down_sync(0xffffffffu, a, o);
            if (tid == 0) hres[1] = a;
        }
        __syncthreads();
        if (tid < 64) arr[tid] = tvs[tid] * ln1b[h * DHd + tid];
        __syncthreads();
        if (tid < 32) {
            float a = arr[tid] + arr[tid + 32];
            #pragma unroll
            for (int o = 16; o > 0; o >>= 1) a += __shfl_down_sync(0xffffffffu, a, o);
            if (tid == 0) hres[2] = a;
        }
        __syncthreads();
        if (tid < 64) arr[tid] = tvs[tid] * x0s[tid];
        __syncthreads();
        if (tid < 32) {
            float a = arr[tid] + arr[tid + 32];
            #pragma unroll
            for (int o = 16; o > 0; o >>= 1) a += __shfl_down_sync(0xffffffffu, a, o);
            if (tid == 0) hres[3] = a;
        }
        __syncthreads();

        if (tid == 0) {
            g_su[h]  = hres[1];
            g_gam[h] = hres[2] + hres[0];
            g_sc0[h] = 32.0f * (hres[3] + hres[0]);
        }
        if (tid < 16) {
            float a = 0.f;
            #pragma unroll 16
            for (int d = 0; d < DHd; d++) a += us[d] * Wp[(h * DHd + d) * 16 + tid];
            g_vproj[h * 16 + tid] = a;
        }
        if (tid < SEQ) {
            int s = tid;
            float a = 0.f;
            for (int d = 0; d < DHd; d++) {
                int gd = h * DHd + d;
                float sa, ca;
                sincosf((float)s * freqs[d], &sa, &ca);
                a += us[d] * ((gd & 1) ? ca : sa);
            }
            g_pep[h * SEQ + s] = a;
        }
    } else if (bid < 99) {
        int h = bid - 83;
        for (int idx = tid; idx < DHd * DHd; idx += 256) {
            int e = idx >> 6, d = idx & 63;
            g_wvT[h * DHd * DHd + d * DHd + e] = Wv[(h * DHd + e) * DHd + d];
        }
    } else if (bid == 99) {
        for (int idx = tid; idx < 16 * Dm; idx += 256) {
            int gd = idx >> 4, p = idx & 15;
            g_wpT[p * Dm + gd] = Wp[gd * 16 + p];
        }
    } else if (bid < 164) {
        // Wm fp16 split: float4 -> 2 packed hi + 2 packed lo words
        int base4 = (bid - 100) * 4096;
        for (int i4 = tid; i4 < 4096; i4 += 256) {
            int idx4 = base4 + i4;
            float4 v = ((const float4*)Wm)[idx4];
            uint32_t h0, l0, h1, l1;
            split_h2(v.x, v.y, h0, l0);
            split_h2(v.z, v.w, h1, l1);
            g_WmHp[2 * idx4]     = h0;
            g_WmHp[2 * idx4 + 1] = h1;
            g_WmLp[2 * idx4]     = l0;
            g_WmLp[2 * idx4 + 1] = l1;
        }
    } else {
        int base4 = (bid - 164) * 4096;
        const int tot4 = NOUT * Dm / 4;
        for (int i4 = tid; i4 < 4096; i4 += 256) {
            int idx4 = base4 + i4;
            if (idx4 < tot4) {
                float4 v = ((const float4*)Wh)[idx4];
                uint32_t h0, l0, h1, l1;
                split_h2(v.x, v.y, h0, l0);
                split_h2(v.z, v.w, h1, l1);
                g_WhHp[2 * idx4]     = h0;
                g_WhHp[2 * idx4 + 1] = h1;
                g_WhLp[2 * idx4]     = l0;
                g_WhLp[2 * idx4 + 1] = l1;
            }
        }
    }
}

// ============================================================================
// K_MAIN: per-batch kernel, BT=4 per block; phase 8 emits packed fp16 planes.
// ============================================================================
#define OFF_PA   0
#define OFF_SCR  (OFF_PA + BT*784)
#define OFF_MU   (OFF_SCR + BT*832)
#define OFF_RSD  (OFF_MU + BT*50)
#define OFF_QT   (OFF_RSD + BT*50)
#define OFF_CC   (OFF_QT + BT*256)
#define OFF_T0P  (OFF_CC + BT*1024)
#define OFF_P0   (OFF_T0P + BT*1024)
#define OFF_MB   (OFF_P0 + BT*16)
#define OFF_RED2 (OFF_MB + BT*16)
#define KMAIN_FLOATS (OFF_RED2 + 16)
#define KMAIN_SMEM (KMAIN_FLOATS * 4)

__global__ __launch_bounds__(512) void k_main(
    const float* __restrict__ x,
    const float* __restrict__ ln1w, const float* __restrict__ ln1b,
    const float* __restrict__ bv,
    const float* __restrict__ ln2w, const float* __restrict__ ln2b)
{
    extern __shared__ float sm[];
    float* pa    = sm + OFF_PA;
    float* scr   = sm + OFF_SCR;
    float* mu    = sm + OFF_MU;
    float* rsd   = sm + OFF_RSD;
    float* qt    = sm + OFF_QT;
    float* cc    = sm + OFF_CC;
    float* t0p   = sm + OFF_T0P;
    float* p0s   = sm + OFF_P0;
    float* mbars = sm + OFF_MB;
    float* red   = sm + OFF_RED2;

    const int b0  = blockIdx.x * BT;
    const int tid = threadIdx.x;
    const int w = tid >> 5, lane = tid & 31;

    if (tid < BT) { mu[tid * 50] = 0.f; rsd[tid * 50] = 0.f; }
    for (int idx = tid; idx < BT * 784; idx += 512) {
        int bt = idx / 784, r = idx % 784;
        int row = r / 28, col = r % 28;
        int pi = (row >> 2) * 7 + (col >> 2);
        int pp = (row & 3) * 4 + (col & 3);
        pa[bt * 784 + pi * 16 + pp] = x[(size_t)(b0 + bt) * 784 + r];
    }
    __syncthreads();

    for (int t = w * 2 + (lane >> 4); t < BT * 49; t += 32) {
        int bt = t / 49, sidx = t % 49, s = sidx + 1;
        int p = lane & 15;
        const float* pr = &pa[bt * 784 + sidx * 16];
        float pap = pr[p];
        float y = 0.f;
        #pragma unroll
        for (int q = 0; q < 16; q++) y += g_G[p * 16 + q] * pr[q];
        float e2p = pap * (y + 2.0f * g_hh[s * 16 + p]);
        float mup = pap * g_cs[p];
        #pragma unroll
        for (int o = 8; o > 0; o >>= 1) {
            e2p += __shfl_down_sync(0xffffffffu, e2p, o, 16);
            mup += __shfl_down_sync(0xffffffffu, mup, o, 16);
        }
        if (p == 0) {
            float m = (mup + g_pesum[s]) * (1.0f / (float)Dm);
            float var = (e2p + g_pesq[s]) * (1.0f / (float)Dm) - m * m;
            mu[bt * 50 + s] = m;
            rsd[bt * 50 + s] = rsqrtf(var + LNEPS);
        }
    }
    __syncthreads();

    for (int t = tid; t < BT * NH * SEQ; t += 512) {
        int bt = t / (NH * SEQ), rem = t % (NH * SEQ);
        int h = rem / SEQ, s = rem % SEQ;
        float v;
        if (s == 0) {
            v = g_sc0[h];
        } else {
            float g = g_pep[h * SEQ + s];
            const float* pr = &pa[bt * 784 + (s - 1) * 16];
            const float* vp = &g_vproj[h * 16];
            #pragma unroll
            for (int p = 0; p < 16; p++) g += pr[p] * vp[p];
            v = 32.0f * (rsd[bt * 50 + s] * (g - mu[bt * 50 + s] * g_su[h]) + g_gam[h]);
        }
        scr[bt * 832 + h * 52 + s] = v;
    }
    __syncthreads();

    for (int task = w; task < BT * NH; task += 16) {
        int bt = task >> 4, h = task & 15;
        float* row = &scr[bt * 832 + h * 52];
        float v1 = row[lane];
        float v2 = (lane + 32 < SEQ) ? row[lane + 32] : -INFINITY;
        float m = fmaxf(v1, v2);
        #pragma unroll
        for (int o = 16; o > 0; o >>= 1) m = fmaxf(m, __shfl_xor_sync(0xffffffffu, m, o));
        float e1 = expf(v1 - m);
        float e2 = (lane + 32 < SEQ) ? expf(v2 - m) : 0.f;
        float ss = e1 + e2;
        #pragma unroll
        for (int o = 16; o > 0; o >>= 1) ss += __shfl_xor_sync(0xffffffffu, ss, o);
        float inv = 1.0f / ss;
        float p1 = e1 * inv, p2 = e2 * inv;
        float r1 = (lane == 0) ? 0.f : p1 * rsd[bt * 50 + lane];
        float r2 = (lane + 32 < SEQ) ? p2 * rsd[bt * 50 + lane + 32] : 0.f;
        row[lane] = r1;
        if (lane + 32 < SEQ) row[lane + 32] = r2;
        float mb = r1 * mu[bt * 50 + lane]
                 + ((lane + 32 < SEQ) ? r2 * mu[bt * 50 + lane + 32] : 0.f);
        #pragma unroll
        for (int o = 16; o > 0; o >>= 1) mb += __shfl_xor_sync(0xffffffffu, mb, o);
        if (lane == 0) { mbars[bt * 16 + h] = mb; p0s[bt * 16 + h] = p1; }
    }
    __syncthreads();

    for (int task = w; task < BT * NH; task += 16) {
        int bt = task >> 4, h = task & 15;
        if (lane < 16) {
            int p = lane;
            const float* rr = &scr[bt * 832 + h * 52];
            const float* pb = &pa[bt * 784];
            float a = 0.f;
            #pragma unroll 7
            for (int sidx = 0; sidx < 49; sidx++)
                a += rr[sidx + 1] * pb[sidx * 16 + p];
            qt[bt * 256 + h * 16 + p] = a;
        }
    }
    __syncthreads();

    for (int gd = tid; gd < Dm; gd += 512) {
        int h = gd >> 6;
        float t1[BT], t2[BT];
        #pragma unroll
        for (int bt = 0; bt < BT; bt++) { t1[bt] = 0.f; t2[bt] = 0.f; }
        #pragma unroll
        for (int p = 0; p < 16; p++) {
            float wv = g_wpT[p * Dm + gd];
            #pragma unroll
            for (int bt = 0; bt < BT; bt++)
                t1[bt] += qt[bt * 256 + h * 16 + p] * wv;
        }
        #pragma unroll 7
        for (int s = 1; s < SEQ; s++) {
            float pev = g_pe[s * Dm + gd];
            #pragma unroll
            for (int bt = 0; bt < BT; bt++)
                t2[bt] += scr[bt * 832 + h * 52 + s] * pev;
        }
        float w1 = ln1w[gd], bb = ln1b[gd], xx0 = g_x0[gd];
        #pragma unroll
        for (int bt = 0; bt < BT; bt++) {
            float p0 = p0s[bt * 16 + h];
            cc[bt * 1024 + gd] = w1 * (t1[bt] + t2[bt] - mbars[bt * 16 + h])
                               + (1.0f - p0) * bb + p0 * xx0;
        }
    }
    __syncthreads();

    for (int ge = tid; ge < Dm; ge += 512) {
        int h = ge >> 6, e = ge & 63;
        float a[BT];
        float bve = bv[ge];
        #pragma unroll
        for (int bt = 0; bt < BT; bt++) a[bt] = bve;
        const float* wvt = &g_wvT[h * DHd * DHd + e];
        #pragma unroll 8
        for (int d = 0; d < DHd; d++) {
            float wvd = wvt[d * DHd];
            #pragma unroll
            for (int bt = 0; bt < BT; bt++)
                a[bt] += wvd * cc[bt * 1024 + h * DHd + d];
        }
        float tk0 = g_tok0[ge];
        #pragma unroll
        for (int bt = 0; bt < BT; bt++)
            t0p[bt * 1024 + ge] = tk0 + a[bt];
    }
    __syncthreads();

    // Phase 8: LN2 + fp16 pack (cc reused as staging for n0 values)
    for (int bt = 0; bt < BT; bt++) {
        float v0 = t0p[bt * 1024 + tid], v1 = t0p[bt * 1024 + tid + 512];
        float s = bred_generic(v0 + v1, red, 16);
        float m = s * (1.0f / (float)Dm);
        float d0 = v0 - m, d1 = v1 - m;
        float q = bred_generic(d0 * d0 + d1 * d1, red, 16);
        float rstd = rsqrtf(q * (1.0f / (float)Dm) + LNEPS);
        size_t base = (size_t)(b0 + bt) * Dm;
        g_tok0p[base + tid]       = v0;
        g_tok0p[base + tid + 512] = v1;
        cc[tid]       = d0 * rstd * ln2w[tid] + ln2b[tid];
        cc[tid + 512] = d1 * rstd * ln2w[tid + 512] + ln2b[tid + 512];
        __syncthreads();
        if (tid < 512) {
            uint32_t hi, lo;
            split_h2(cc[2 * tid], cc[2 * tid + 1], hi, lo);
            size_t bw = (size_t)(b0 + bt) * 512 + tid;
            g_aHp[bw] = hi;
            g_aLp[bw] = lo;
        }
        __syncthreads();
    }
}

// ============================================================================
// GEMM (3-term fp16 split, m16n8k16, cp.async 2-stage pipeline).
// 128x64 CTA tile, 8 warps (32x32 each, 4m x 2n), BK=32 halves (16 words),
// grid (16, 8) = 128 CTAs (single wave). Packed planes, row stride 20 words.
// ============================================================================
__device__ __forceinline__ void mma_f16(float c[4], const uint32_t a[4],
                                        const uint32_t b[2]) {
    asm volatile(
        "mma.sync.aligned.m16n8k16.row.col.f32.f16.f16.f32 "
        "{%0,%1,%2,%3}, {%4,%5,%6,%7}, {%8,%9}, {%0,%1,%2,%3};\n"
        : "+f"(c[0]), "+f"(c[1]), "+f"(c[2]), "+f"(c[3])
        : "r"(a[0]), "r"(a[1]), "r"(a[2]), "r"(a[3]), "r"(b[0]), "r"(b[1]));
}

__device__ __forceinline__ uint32_t smem_u32g(const void* p) {
    uint32_t a;
    asm("{ .reg .u64 t; cvta.to.shared.u64 t, %1; cvt.u32.u64 %0, t; }"
        : "=r"(a) : "l"(p));
    return a;
}

__device__ __forceinline__ void cpa16(uint32_t dst, const uint32_t* src, int ssz) {
    asm volatile("cp.async.cg.shared.global [%0], [%1], 16, %2;"
                 :: "r"(dst), "l"(src), "r"(ssz) : "memory");
}

// slab (uint32 words): Ah[128*20]=2560 | Al 2560 | Bh[64*20]=1280 | Bl 1280
// slab = 7680 words = 30720 B; double buffer = 61440 B dynamic smem
#define GEMM_SMEM 61440

__device__ __forceinline__ void tc_comp_h(
    const uint32_t* Ah, const uint32_t* Al,
    const uint32_t* Bh, const uint32_t* Bl,
    float (&c)[2][4][4], int wm, int wn, int gid, int tg)
{
    #pragma unroll
    for (int ks = 0; ks < 2; ks++) {
        const int kw = ks * 8;
        uint32_t ah[2][4], al[2][4], bh[4][2], bl[4][2];
        #pragma unroll
        for (int i = 0; i < 2; i++) {
            int m = wm + i * 16 + gid;
            ah[i][0] = Ah[m * 20 + kw + tg];
            ah[i][1] = Ah[(m + 8) * 20 + kw + tg];
            ah[i][2] = Ah[m * 20 + kw + tg + 4];
            ah[i][3] = Ah[(m + 8) * 20 + kw + tg + 4];
            al[i][0] = Al[m * 20 + kw + tg];
            al[i][1] = Al[(m + 8) * 20 + kw + tg];
            al[i][2] = Al[m * 20 + kw + tg + 4];
            al[i][3] = Al[(m + 8) * 20 + kw + tg + 4];
        }
        #pragma unroll
        for (int j = 0; j < 4; j++) {
            int n = wn + j * 8 + gid;
            bh[j][0] = Bh[n * 20 + kw + tg];
            bh[j][1] = Bh[n * 20 + kw + tg + 4];
            bl[j][0] = Bl[n * 20 + kw + tg];
            bl[j][1] = Bl[n * 20 + kw + tg + 4];
        }
        #pragma unroll
        for (int i = 0; i < 2; i++)
            #pragma unroll
            for (int j = 0; j < 4; j++) {
                mma_f16(c[i][j], ah[i], bh[j]);
                mma_f16(c[i][j], ah[i], bl[j]);
                mma_f16(c[i][j], al[i], bh[j]);
            }
    }
}

template <bool HAS_RES, bool SPLIT_OUT>
__global__ __launch_bounds__(256) void gemm_h(
    const uint32_t* __restrict__ AH, const uint32_t* __restrict__ AL,
    const uint32_t* __restrict__ BH, const uint32_t* __restrict__ BL,
    const float* __restrict__ bias, const float* __restrict__ Res,
    float* __restrict__ C, uint32_t* __restrict__ CH, uint32_t* __restrict__ CL,
    int M, int N, int K)
{
    extern __shared__ uint32_t smw[];
    const int tid = threadIdx.x;
    const int warp = tid >> 5, lane = tid & 31;
    const int wm = (warp & 3) * 32;        // 4 m-warps over 128 rows
    const int wn = (warp >> 2) * 32;       // 2 n-warps over 64 cols
    const int m0 = blockIdx.y * 128, n0 = blockIdx.x * 64;
    const int gid = lane >> 2, tg = lane & 3;
    const int KW = K >> 1;                 // words per row (512)

    float c[2][4][4];
    #pragma unroll
    for (int i = 0; i < 2; i++)
        #pragma unroll
        for (int j = 0; j < 4; j++)
            #pragma unroll
            for (int q = 0; q < 4; q++) c[i][j][q] = 0.f;

    // A loader: 128 rows x 4 chunks(16B=4 words) = 512 chunks / 256 thr = 2 each
    const int ra = tid >> 1;
    const int ca = (tid & 1) * 8;          // word offsets ca, ca+4
    const uint32_t* gAH = AH + (size_t)(m0 + ra) * KW + ca;
    const uint32_t* gAL = AL + (size_t)(m0 + ra) * KW + ca;
    // B loader: 64 rows x 4 chunks = 256 chunks / 256 thr = 1 each
    const int rb = tid >> 2;
    const int cb = (tid & 3) * 4;
    const int nr = n0 + rb;
    const int nok = (nr < N) ? 16 : 0;
    const uint32_t* gBH = BH + (size_t)(nr < N ? nr : 0) * KW + cb;
    const uint32_t* gBL = BL + (size_t)(nr < N ? nr : 0) * KW + cb;

    const uint32_t smb = smem_u32g(smw);
    const uint32_t dA = smb + (uint32_t)(ra * 20 + ca) * 4u;
    const uint32_t dB = smb + 20480u + (uint32_t)(rb * 20 + cb) * 4u;

    // prologue: slab 0 -> buffer 0
    {
        cpa16(dA,          gAH, 16);
        cpa16(dA + 16,     gAH + 4, 16);
        cpa16(dA + 10240,  gAL, 16);
        cpa16(dA + 10256,  gAL + 4, 16);
        cpa16(dB,          gBH, nok);
        cpa16(dB + 5120,   gBL, nok);
        asm volatile("cp.async.commit_group;" ::: "memory");
    }

    const int NSLAB = KW / 16;   // 32
    for (int s = 0; s < NSLAB; s++) {
        asm volatile("cp.async.wait_group 0;" ::: "memory");
        __syncthreads();
        if (s + 1 < NSLAB) {
            int koff = (s + 1) * 16;
            uint32_t boff = (uint32_t)((s + 1) & 1) * 30720u;
            cpa16(dA + boff,          gAH + koff, 16);
            cpa16(dA + boff + 16,     gAH + koff + 4, 16);
            cpa16(dA + boff + 10240,  gAL + koff, 16);
            cpa16(dA + boff + 10256,  gAL + koff + 4, 16);
            cpa16(dB + boff,          gBH + koff, nok);
            cpa16(dB + boff + 5120,   gBL + koff, nok);
            asm volatile("cp.async.commit_group;" ::: "memory");
        }
        const uint32_t* base = smw + (s & 1) * 7680;
        tc_comp_h(base, base + 2560, base + 5120, base + 6400,
                  c, wm, wn, gid, tg);
    }

    // epilogue: q-pairs (0,1)/(2,3) are (row, col) and (row, col+1)
    #pragma unroll
    for (int i = 0; i < 2; i++) {
        #pragma unroll
        for (int j = 0; j < 4; j++) {
            int row0 = m0 + wm + i * 16 + gid;
            int colb = n0 + wn + j * 8 + 2 * tg;   // even
            #pragma unroll
            for (int r2 = 0; r2 < 2; r2++) {
                int row = row0 + r2 * 8;
                float v0 = c[i][j][r2 * 2];
                float v1 = c[i][j][r2 * 2 + 1];
                if (colb < N)     v0 += bias[colb];
                if (colb + 1 < N) v1 += bias[colb + 1];
                if (HAS_RES) {
                    v0 += Res[(size_t)row * N + colb];
                    v1 += Res[(size_t)row * N + colb + 1];
                }
                if (SPLIT_OUT) {
                    uint32_t hi, lo;
                    split_h2(v0, v1, hi, lo);
                    size_t wi = (size_t)row * (N >> 1) + (colb >> 1);
                    CH[wi] = hi;
                    CL[wi] = lo;
                } else {
                    if (colb < N)     C[(size_t)row * N + colb] = v0;
                    if (colb + 1 < N) C[(size_t)row * N + colb + 1] = v1;
                }
            }
        }
    }
}

// ---------------- softmax over 1000 logits (in-place on d_out) ---------------
__global__ __launch_bounds__(256) void softmax_kernel(float* __restrict__ out) {
    int b = blockIdx.x, tid = threadIdx.x;
    __shared__ float red[32];
    int lane = tid & 31, w = tid >> 5;
    float v[4];
    float m = -INFINITY;
    #pragma unroll
    for (int u = 0; u < 4; u++) {
        int j = tid + 256 * u;
        v[u] = (j < NOUT) ? out[(size_t)b * NOUT + j] : -INFINITY;
        m = fmaxf(m, v[u]);
    }
    #pragma unroll
    for (int o = 16; o > 0; o >>= 1) m = fmaxf(m, __shfl_xor_sync(0xffffffffu, m, o));
    if (lane == 0) red[w] = m;
    __syncthreads();
    if (tid < 8) {
        float x2 = red[tid];
        #pragma unroll
        for (int o = 4; o > 0; o >>= 1) x2 = fmaxf(x2, __shfl_xor_sync(0xffu, x2, o));
        if (tid == 0) red[0] = x2;
    }
    __syncthreads();
    m = red[0];
    __syncthreads();
    float s = 0.f;
    #pragma unroll
    for (int u = 0; u < 4; u++) {
        int j = tid + 256 * u;
        if (j < NOUT) { v[u] = expf(v[u] - m); s += v[u]; }
    }
    #pragma unroll
    for (int o = 16; o > 0; o >>= 1) s += __shfl_xor_sync(0xffffffffu, s, o);
    if (lane == 0) red[w] = s;
    __syncthreads();
    if (tid < 8) {
        float x2 = red[tid];
        #pragma unroll
        for (int o = 4; o > 0; o >>= 1) x2 += __shfl_xor_sync(0xffu, x2, o);
        if (tid == 0) red[0] = x2;
    }
    __syncthreads();
    float inv = 1.0f / red[0];
    #pragma unroll
    for (int u = 0; u < 4; u++) {
        int j = tid + 256 * u;
        if (j < NOUT) out[(size_t)b * NOUT + j] = v[u] * inv;
    }
}

// ---------------- launch ------------------------------------------------------
extern "C" void kernel_launch(void* const* d_in, const int* in_sizes, int n_in,
                              void* d_out, int out_size) {
    const float* x    = (const float*)d_in[0];
    const float* cls  = (const float*)d_in[1];
    const float* Wp   = (const float*)d_in[2];
    const float* ln1w = (const float*)d_in[3];
    const float* ln1b = (const float*)d_in[4];
    const float* Wq   = (const float*)d_in[5];
    const float* bq   = (const float*)d_in[6];
    const float* Wk   = (const float*)d_in[7];
    const float* bk   = (const float*)d_in[8];
    const float* Wv   = (const float*)d_in[9];
    const float* bv   = (const float*)d_in[10];
    const float* ln2w = (const float*)d_in[11];
    const float* ln2b = (const float*)d_in[12];
    const float* Wm   = (const float*)d_in[13];
    const float* bm   = (const float*)d_in[14];
    const float* Wh   = (const float*)d_in[15];
    const float* bh   = (const float*)d_in[16];
    float* out = (float*)d_out;

    uint32_t *p_aHp, *p_aLp, *p_fHp, *p_fLp, *p_WmHp, *p_WmLp, *p_WhHp, *p_WhLp;
    float* p_tok0p;
    cudaGetSymbolAddress((void**)&p_aHp, g_aHp);
    cudaGetSymbolAddress((void**)&p_aLp, g_aLp);
    cudaGetSymbolAddress((void**)&p_fHp, g_fHp);
    cudaGetSymbolAddress((void**)&p_fLp, g_fLp);
    cudaGetSymbolAddress((void**)&p_WmHp, g_WmHp);
    cudaGetSymbolAddress((void**)&p_WmLp, g_WmLp);
    cudaGetSymbolAddress((void**)&p_WhHp, g_WhHp);
    cudaGetSymbolAddress((void**)&p_WhLp, g_WhLp);
    cudaGetSymbolAddress((void**)&p_tok0p, g_tok0p);

    cudaFuncSetAttribute(k_main, cudaFuncAttributeMaxDynamicSharedMemorySize,
                         KMAIN_SMEM);
    cudaFuncSetAttribute(gemm_h<true, true>,
                         cudaFuncAttributeMaxDynamicSharedMemorySize, GEMM_SMEM);
    cudaFuncSetAttribute(gemm_h<false, false>,
                         cudaFuncAttributeMaxDynamicSharedMemorySize, GEMM_SMEM);

    k_pre<<<227, 256>>>(Wp, cls, ln1w, ln1b, Wq, bq, Wk, bk, Wv, Wm, Wh);
    k_main<<<Bsz / BT, 512, KMAIN_SMEM>>>(x, ln1w, ln1b, bv, ln2w, ln2b);
    gemm_h<true, true><<<dim3(16, 8), 256, GEMM_SMEM>>>(
        p_aHp, p_aLp, p_WmHp, p_WmLp, bm, p_tok0p,
        nullptr, p_fHp, p_fLp, Bsz, Dm, Dm);
    gemm_h<false, false><<<dim3(16, 8), 256, GEMM_SMEM>>>(
        p_fHp, p_fLp, p_WhHp, p_WhLp, bh, nullptr,
        out, nullptr, nullptr, Bsz, NOUT, Dm);
    softmax_kernel<<<Bsz, 256>>>(out);
}